// round 1
// baseline (speedup 1.0000x reference)
#include <cuda_runtime.h>
#include <math.h>

// Attention_49194555408812: out[b,h,d,q] = softmax_k(leakyrelu(q^T k / 8)) @ v^T
// Shapes: B=4, H=8, D=64, L=2048, fp32. Layout [B,H,D,L] (L contiguous).

namespace {
constexpr int D       = 64;
constexpr int LEN     = 2048;
constexpr int TQ      = 64;
constexpr int TK      = 64;
constexpr float SCALE = 0.125f;   // 1/sqrt(64)
constexpr float NSLOPE = 0.01f;
}  // namespace

#define FMA16(a, b, s)                      \
    s[0][0] = fmaf(a.x, b.x, s[0][0]);      \
    s[0][1] = fmaf(a.x, b.y, s[0][1]);      \
    s[0][2] = fmaf(a.x, b.z, s[0][2]);      \
    s[0][3] = fmaf(a.x, b.w, s[0][3]);      \
    s[1][0] = fmaf(a.y, b.x, s[1][0]);      \
    s[1][1] = fmaf(a.y, b.y, s[1][1]);      \
    s[1][2] = fmaf(a.y, b.z, s[1][2]);      \
    s[1][3] = fmaf(a.y, b.w, s[1][3]);      \
    s[2][0] = fmaf(a.z, b.x, s[2][0]);      \
    s[2][1] = fmaf(a.z, b.y, s[2][1]);      \
    s[2][2] = fmaf(a.z, b.z, s[2][2]);      \
    s[2][3] = fmaf(a.z, b.w, s[2][3]);      \
    s[3][0] = fmaf(a.w, b.x, s[3][0]);      \
    s[3][1] = fmaf(a.w, b.y, s[3][1]);      \
    s[3][2] = fmaf(a.w, b.z, s[3][2]);      \
    s[3][3] = fmaf(a.w, b.w, s[3][3]);

// One CTA = one (head, 64-query tile). 256 threads = 16x16 grid of 4x4 micro-tiles.
__global__ void __launch_bounds__(256, 2)
attn_flash_fp32(const float* __restrict__ q,
                const float* __restrict__ k,
                const float* __restrict__ v,
                float* __restrict__ out) {
    extern __shared__ float smem[];
    float* Qs = smem;                 // [64][64]  (d, q)   16 KB
    float* Ks = Qs + D * TK;          // [64][64]  (d, kl)  16 KB
    float* Vt = Ks + D * TK;          // [64][64]  (kl, d)  16 KB  (transposed)
    float* Pt = Vt + D * TK;          // [64][64]  (kl, q)  16 KB
    float* m_s = Pt + TK * TQ;        // [64] running max per query
    float* l_s = m_s + TQ;            // [64] running sum per query
    float* f_s = l_s + TQ;            // [64] per-tile rescale factor per query

    const int tid = threadIdx.x;
    const int tx  = tid & 15;         // q  micro-tile column group / kl in S
    const int ty  = tid >> 4;         // d/q micro-tile row group
    const int bh  = blockIdx.y;
    const int qt  = blockIdx.x * TQ;
    const size_t base = (size_t)bh * D * LEN;

    const int lr = tid >> 4;          // load row   (0..15)
    const int lc = (tid & 15) << 2;   // load col*4 (0..60)

    // ---- load Q tile [d][q], coalesced float4 ----
#pragma unroll
    for (int d = lr; d < D; d += 16) {
        float4 t = *(const float4*)(q + base + (size_t)d * LEN + qt + lc);
        *(float4*)&Qs[d * TQ + lc] = t;
    }
    if (tid < TQ) { m_s[tid] = -INFINITY; l_s[tid] = 0.0f; }

    float acc[4][4] = {};

    for (int kt = 0; kt < LEN; kt += TK) {
        __syncthreads();   // prev PV done; stats init visible on first iter

        // ---- load K tile [d][kl]; V tile transposed -> Vt[kl][d] ----
#pragma unroll
        for (int d = lr; d < D; d += 16) {
            float4 kk = *(const float4*)(k + base + (size_t)d * LEN + kt + lc);
            *(float4*)&Ks[d * TK + lc] = kk;
            float4 vv = *(const float4*)(v + base + (size_t)d * LEN + kt + lc);
            Vt[(lc + 0) * D + d] = vv.x;
            Vt[(lc + 1) * D + d] = vv.y;
            Vt[(lc + 2) * D + d] = vv.z;
            Vt[(lc + 3) * D + d] = vv.w;
        }
        __syncthreads();

        // ---- S = Q^T K (4x4 micro-tile per thread) ----
        float s[4][4] = {};
#pragma unroll 16
        for (int d = 0; d < D; ++d) {
            const float4 a = *(const float4*)(Qs + d * TQ + (ty << 2));
            const float4 b = *(const float4*)(Ks + d * TK + (tx << 2));
            FMA16(a, b, s)
        }

        // ---- scale + LeakyReLU + row max ----
        float rmax[4];
#pragma unroll
        for (int i = 0; i < 4; ++i) {
            rmax[i] = -INFINITY;
#pragma unroll
            for (int j = 0; j < 4; ++j) {
                float x = s[i][j] * SCALE;
                x = (x > 0.0f) ? x : NSLOPE * x;
                s[i][j] = x;
                rmax[i] = fmaxf(rmax[i], x);
            }
        }
#pragma unroll
        for (int i = 0; i < 4; ++i) {
#pragma unroll
            for (int off = 8; off >= 1; off >>= 1)
                rmax[i] = fmaxf(rmax[i], __shfl_xor_sync(0xffffffffu, rmax[i], off));
        }

        // ---- online softmax: p = exp(s - m_new), row sums ----
        float m_old[4], m_new[4], rsum[4], p[4][4];
#pragma unroll
        for (int i = 0; i < 4; ++i) {
            m_old[i] = m_s[(ty << 2) + i];
            m_new[i] = fmaxf(m_old[i], rmax[i]);
            rsum[i] = 0.0f;
#pragma unroll
            for (int j = 0; j < 4; ++j) {
                p[i][j] = __expf(s[i][j] - m_new[i]);
                rsum[i] += p[i][j];
            }
        }
#pragma unroll
        for (int i = 0; i < 4; ++i) {
#pragma unroll
            for (int off = 8; off >= 1; off >>= 1)
                rsum[i] += __shfl_xor_sync(0xffffffffu, rsum[i], off);
        }

        __syncwarp();   // all lanes finished reading m_s/l_s rows before tx==0 writes
        if (tx == 0) {
#pragma unroll
            for (int i = 0; i < 4; ++i) {
                const int r = (ty << 2) + i;
                const float f = __expf(m_old[i] - m_new[i]);
                f_s[r] = f;
                l_s[r] = l_s[r] * f + rsum[i];
                m_s[r] = m_new[i];
            }
        }

        // ---- store P transposed: Pt[kl][q], float4 down the q axis ----
#pragma unroll
        for (int j = 0; j < 4; ++j) {
            float4 t = make_float4(p[0][j], p[1][j], p[2][j], p[3][j]);
            *(float4*)&Pt[((tx << 2) + j) * TQ + (ty << 2)] = t;
        }
        __syncthreads();

        // ---- rescale running O, then O += V P^T ----
        const float4 f4 = *(const float4*)&f_s[tx << 2];
        const float fj[4] = {f4.x, f4.y, f4.z, f4.w};
#pragma unroll
        for (int i = 0; i < 4; ++i)
#pragma unroll
            for (int j = 0; j < 4; ++j)
                acc[i][j] *= fj[j];

#pragma unroll 16
        for (int kl = 0; kl < TK; ++kl) {
            const float4 a = *(const float4*)(Vt + kl * D + (ty << 2));  // d rows
            const float4 b = *(const float4*)(Pt + kl * TQ + (tx << 2)); // q cols
            FMA16(a, b, acc)
        }
    }

    // ---- normalize and write out[d][q] (float4 along q) ----
    const float4 l4 = *(const float4*)&l_s[tx << 2];
    const float linv[4] = {1.0f / l4.x, 1.0f / l4.y, 1.0f / l4.z, 1.0f / l4.w};
#pragma unroll
    for (int i = 0; i < 4; ++i) {
        float4 o = make_float4(acc[i][0] * linv[0], acc[i][1] * linv[1],
                               acc[i][2] * linv[2], acc[i][3] * linv[3]);
        *(float4*)(out + base + (size_t)((ty << 2) + i) * LEN + qt + (tx << 2)) = o;
    }
}

extern "C" void kernel_launch(void* const* d_in, const int* in_sizes, int n_in,
                              void* d_out, int out_size) {
    const float* q = (const float*)d_in[0];
    const float* k = (const float*)d_in[1];
    const float* v = (const float*)d_in[2];
    float* out = (float*)d_out;

    const int heads = in_sizes[0] / (D * LEN);   // B*H = 32
    const int smem_bytes = (4 * D * TK + 3 * TQ) * (int)sizeof(float);  // 66304 B

    cudaFuncSetAttribute(attn_flash_fp32,
                         cudaFuncAttributeMaxDynamicSharedMemorySize, smem_bytes);

    dim3 grid(LEN / TQ, heads);
    attn_flash_fp32<<<grid, 256, smem_bytes>>>(q, k, v, out);
}

// round 3
// speedup vs baseline: 3.8345x; 3.8345x over previous
#include <cuda_runtime.h>
#include <cuda_bf16.h>
#include <stdint.h>

// Attention_49194555408812 via mma.sync bf16-split (fp32 emulated), sm_103-safe.
// out[b,h,d,q] = softmax_k(leakyrelu(q^T k / 8)) @ v^T
// B*H=32, D=64, L=2048, fp32, layout [B,H,D,L] (L contiguous).

namespace {
constexpr int D   = 64;
constexpr int LEN = 2048;
constexpr int TQ  = 128;        // queries per CTA (8 warps x m16)
constexpr int TK  = 64;         // key tile
constexpr int NT  = LEN / TK;   // 32
constexpr float SCALE  = 0.125f;
constexpr float NSLOPE = 0.01f;

// smem: Q [d=64][q=128] bf16 (256B rows), K/V [d=64][kl=64] bf16 (128B rows)
constexpr int OFF_QH = 0;
constexpr int OFF_QL = 16384;
constexpr int OFF_KH = 32768;
constexpr int OFF_KL = 40960;
constexpr int OFF_VH = 49152;
constexpr int OFF_VL = 57344;
constexpr int SMEM_TOTAL = 65536;
}  // namespace

__device__ __forceinline__ uint32_t swz256(uint32_t o) { return o ^ ((o >> 4) & 0x70); }
__device__ __forceinline__ uint32_t swz128(uint32_t o) { return o ^ ((o >> 3) & 0x70); }

__device__ __forceinline__ uint32_t smem_u32(const void* p) {
    uint32_t a;
    asm("{ .reg .u64 t; cvta.to.shared.u64 t, %1; cvt.u32.u64 %0, t; }" : "=r"(a) : "l"(p));
    return a;
}

__device__ __forceinline__ void ldsm_x4_t(uint32_t addr, uint32_t& r0, uint32_t& r1,
                                          uint32_t& r2, uint32_t& r3) {
    asm volatile("ldmatrix.sync.aligned.m8n8.x4.trans.shared.b16 {%0,%1,%2,%3}, [%4];"
                 : "=r"(r0), "=r"(r1), "=r"(r2), "=r"(r3) : "r"(addr));
}
__device__ __forceinline__ void ldsm_x4(uint32_t addr, uint32_t& r0, uint32_t& r1,
                                        uint32_t& r2, uint32_t& r3) {
    asm volatile("ldmatrix.sync.aligned.m8n8.x4.shared.b16 {%0,%1,%2,%3}, [%4];"
                 : "=r"(r0), "=r"(r1), "=r"(r2), "=r"(r3) : "r"(addr));
}

__device__ __forceinline__ void mma16816(float c[4], const uint32_t a[4],
                                         uint32_t b0, uint32_t b1) {
    asm volatile(
        "mma.sync.aligned.m16n8k16.row.col.f32.bf16.bf16.f32 "
        "{%0,%1,%2,%3}, {%4,%5,%6,%7}, {%8,%9}, {%0,%1,%2,%3};"
        : "+f"(c[0]), "+f"(c[1]), "+f"(c[2]), "+f"(c[3])
        : "r"(a[0]), "r"(a[1]), "r"(a[2]), "r"(a[3]), "r"(b0), "r"(b1));
}

// split float4 into bf16-hi pair-packed and bf16-lo pair-packed (2x uint32 each)
__device__ __forceinline__ void split4(float4 f, uint2& h, uint2& l) {
    __nv_bfloat162 ha = __floats2bfloat162_rn(f.x, f.y);
    __nv_bfloat162 hb = __floats2bfloat162_rn(f.z, f.w);
    __nv_bfloat162 la = __floats2bfloat162_rn(f.x - __bfloat162float(ha.x),
                                              f.y - __bfloat162float(ha.y));
    __nv_bfloat162 lb = __floats2bfloat162_rn(f.z - __bfloat162float(hb.x),
                                              f.w - __bfloat162float(hb.y));
    h.x = *reinterpret_cast<uint32_t*>(&ha);
    h.y = *reinterpret_cast<uint32_t*>(&hb);
    l.x = *reinterpret_cast<uint32_t*>(&la);
    l.y = *reinterpret_cast<uint32_t*>(&lb);
}

// pack two f32 into bf16x2 hi + residual lo
__device__ __forceinline__ void pack_hl(float a, float b, uint32_t& h, uint32_t& l) {
    __nv_bfloat162 hh = __floats2bfloat162_rn(a, b);
    __nv_bfloat162 ll = __floats2bfloat162_rn(a - __bfloat162float(hh.x),
                                              b - __bfloat162float(hh.y));
    h = *reinterpret_cast<uint32_t*>(&hh);
    l = *reinterpret_cast<uint32_t*>(&ll);
}

__global__ void __launch_bounds__(256, 1)
attn_mma(const float* __restrict__ qg, const float* __restrict__ kg,
         const float* __restrict__ vg, float* __restrict__ outg) {
    extern __shared__ __align__(1024) char smem[];
    const uint32_t sb = smem_u32(smem);

    const int tid  = threadIdx.x;
    const int wid  = tid >> 5;
    const int lane = tid & 31;
    const int sub  = lane >> 3;   // ldmatrix lane group 0..3
    const int li   = lane & 7;    // row within group
    const int bh   = blockIdx.y;
    const int qt   = blockIdx.x * TQ;
    const size_t base = (size_t)bh * D * LEN;

    // ---- Q prolog: [d][q] direct layout, scaled, bf16 hi/lo split ----
#pragma unroll
    for (int i = 0; i < 8; ++i) {
        const int idx = i * 256 + tid;
        const int d = idx >> 5, c4 = idx & 31;   // 32 float4 per 128-wide row
        float4 f = *(const float4*)(qg + base + (size_t)d * LEN + qt + c4 * 4);
        f.x *= SCALE; f.y *= SCALE; f.z *= SCALE; f.w *= SCALE;
        uint2 h, l;
        split4(f, h, l);
        const uint32_t off = d * 256 + c4 * 8;
        *(uint2*)(smem + OFF_QH + swz256(off)) = h;
        *(uint2*)(smem + OFF_QL + swz256(off)) = l;
    }
    __syncthreads();

    // ---- Q fragments to registers (A of GEMM1, m=q rows 16*wid.., k=d) ----
    uint32_t QHf[4][4], QLf[4][4];
    {
        const int q0 = wid * 16 + ((sub & 1) << 3);
#pragma unroll
        for (int j = 0; j < 4; ++j) {
            const int dr = 16 * j + ((sub >> 1) << 3) + li;
            ldsm_x4_t(sb + OFF_QH + swz256(dr * 256 + q0 * 2),
                      QHf[j][0], QHf[j][1], QHf[j][2], QHf[j][3]);
            ldsm_x4_t(sb + OFF_QL + swz256(dr * 256 + q0 * 2),
                      QLf[j][0], QLf[j][1], QLf[j][2], QLf[j][3]);
        }
    }

    float O[8][4];
#pragma unroll
    for (int n = 0; n < 8; ++n)
#pragma unroll
        for (int c = 0; c < 4; ++c) O[n][c] = 0.0f;
    float rsum0 = 0.0f, rsum1 = 0.0f;

    for (int t = 0; t < NT; ++t) {
        if (t) __syncthreads();   // GEMM2 of prev tile done reading Vs
        const int kt = t * TK;

        // ---- K/V tile: [d][kl] direct layout, bf16 hi/lo split ----
#pragma unroll
        for (int i = 0; i < 4; ++i) {
            const int idx = i * 256 + tid;
            const int d = idx >> 4, c4 = idx & 15;
            const uint32_t off = d * 128 + c4 * 8;
            float4 f = *(const float4*)(kg + base + (size_t)d * LEN + kt + c4 * 4);
            uint2 h, l;
            split4(f, h, l);
            *(uint2*)(smem + OFF_KH + swz128(off)) = h;
            *(uint2*)(smem + OFF_KL + swz128(off)) = l;
            f = *(const float4*)(vg + base + (size_t)d * LEN + kt + c4 * 4);
            split4(f, h, l);
            *(uint2*)(smem + OFF_VH + swz128(off)) = h;
            *(uint2*)(smem + OFF_VL + swz128(off)) = l;
        }
        __syncthreads();

        // ---- GEMM1: S[16q][64kl] = Q·K^T  (hi*hi + lo*hi + hi*lo) ----
        float S[8][4];
#pragma unroll
        for (int n = 0; n < 8; ++n)
#pragma unroll
            for (int c = 0; c < 4; ++c) S[n][c] = 0.0f;

#pragma unroll
        for (int j = 0; j < 4; ++j) {           // kstep over d
            const int dr = 16 * j + ((sub & 1) << 3) + li;
#pragma unroll
            for (int np = 0; np < 4; ++np) {    // n-pairs over kl
                const int nc = 16 * np + ((sub >> 1) << 3);
                uint32_t b0, b1, b2, b3;
                ldsm_x4_t(sb + OFF_KH + swz128(dr * 128 + nc * 2), b0, b1, b2, b3);
                mma16816(S[2 * np],     QHf[j], b0, b1);
                mma16816(S[2 * np + 1], QHf[j], b2, b3);
                mma16816(S[2 * np],     QLf[j], b0, b1);
                mma16816(S[2 * np + 1], QLf[j], b2, b3);
                ldsm_x4_t(sb + OFF_KL + swz128(dr * 128 + nc * 2), b0, b1, b2, b3);
                mma16816(S[2 * np],     QHf[j], b0, b1);
                mma16816(S[2 * np + 1], QHf[j], b2, b3);
            }
        }

        // ---- leakyrelu + exp + row sums (no max shift: scores bounded) ----
        float t0 = 0.0f, t1 = 0.0f;
#pragma unroll
        for (int n = 0; n < 8; ++n) {
#pragma unroll
            for (int c = 0; c < 4; ++c) {
                float x = S[n][c];
                x = fmaxf(x, NSLOPE * x);   // leakyrelu
                S[n][c] = __expf(x);
            }
            t0 += S[n][0] + S[n][1];
            t1 += S[n][2] + S[n][3];
        }
        t0 += __shfl_xor_sync(0xffffffffu, t0, 1);
        t0 += __shfl_xor_sync(0xffffffffu, t0, 2);
        t1 += __shfl_xor_sync(0xffffffffu, t1, 1);
        t1 += __shfl_xor_sync(0xffffffffu, t1, 2);
        rsum0 += t0;
        rsum1 += t1;

        // ---- GEMM2: O[16q][64d] += P·V^T, P repacked in-register ----
#pragma unroll
        for (int j = 0; j < 4; ++j) {           // kstep over kl
            uint32_t ah[4], al[4];
            pack_hl(S[2 * j][0],     S[2 * j][1],     ah[0], al[0]);
            pack_hl(S[2 * j][2],     S[2 * j][3],     ah[1], al[1]);
            pack_hl(S[2 * j + 1][0], S[2 * j + 1][1], ah[2], al[2]);
            pack_hl(S[2 * j + 1][2], S[2 * j + 1][3], ah[3], al[3]);
            const int kc = 16 * j + ((sub & 1) << 3);
#pragma unroll
            for (int dp = 0; dp < 4; ++dp) {    // n-pairs over d
                const int dr = 16 * dp + ((sub >> 1) << 3) + li;
                uint32_t b0, b1, b2, b3;
                ldsm_x4(sb + OFF_VH + swz128(dr * 128 + kc * 2), b0, b1, b2, b3);
                mma16816(O[2 * dp],     ah, b0, b1);
                mma16816(O[2 * dp + 1], ah, b2, b3);
                mma16816(O[2 * dp],     al, b0, b1);
                mma16816(O[2 * dp + 1], al, b2, b3);
                ldsm_x4(sb + OFF_VL + swz128(dr * 128 + kc * 2), b0, b1, b2, b3);
                mma16816(O[2 * dp],     ah, b0, b1);
                mma16816(O[2 * dp + 1], ah, b2, b3);
            }
        }
    }

    // ---- normalize + store out[d][q] ----
    const float inv0 = 1.0f / rsum0;
    const float inv1 = 1.0f / rsum1;
    float* op = outg + base + qt + wid * 16 + (lane >> 2);
#pragma unroll
    for (int n = 0; n < 8; ++n) {
        const int d0 = 8 * n + 2 * (lane & 3);
        op[(size_t)d0 * LEN]           = O[n][0] * inv0;
        op[(size_t)(d0 + 1) * LEN]     = O[n][1] * inv0;
        op[(size_t)d0 * LEN + 8]       = O[n][2] * inv1;
        op[(size_t)(d0 + 1) * LEN + 8] = O[n][3] * inv1;
    }
}

extern "C" void kernel_launch(void* const* d_in, const int* in_sizes, int n_in,
                              void* d_out, int out_size) {
    const float* q = (const float*)d_in[0];
    const float* k = (const float*)d_in[1];
    const float* v = (const float*)d_in[2];
    float* out = (float*)d_out;

    const int heads = in_sizes[0] / (D * LEN);   // 32
    cudaFuncSetAttribute(attn_mma, cudaFuncAttributeMaxDynamicSharedMemorySize, SMEM_TOTAL);
    dim3 grid(LEN / TQ, heads);                  // (16, 32) = 512 CTAs
    attn_mma<<<grid, 256, SMEM_TOTAL>>>(q, k, v, out);
}

// round 4
// speedup vs baseline: 4.0718x; 1.0619x over previous
#include <cuda_runtime.h>
#include <cuda_bf16.h>
#include <stdint.h>

// Attention_49194555408812: mma.sync bf16-split (3-pass fp32 emulation), sm_103-safe.
// Round 4: pre-pass converts Q(scaled)/K/V to bf16 hi/lo in global scratch once;
// main kernel streams tiles with double-buffered cp.async (no conversion in loop).

namespace {
constexpr int D   = 64;
constexpr int LEN = 2048;
constexpr int BH  = 32;         // B*H
constexpr int TQ  = 128;
constexpr int TK  = 64;
constexpr int NT  = LEN / TK;   // 32
constexpr float SCALE  = 0.125f;
constexpr float NSLOPE = 0.01f;
constexpr int NELEM = BH * D * LEN;       // 4,194,304 per tensor

// smem: QH/QL [d=64][q=128] bf16 (256B rows); 2 stages of K/V hi+lo [d=64][kl=64]
constexpr int OFF_QH   = 0;
constexpr int OFF_QL   = 16384;
constexpr int OFF_ST   = 32768;           // stage s at OFF_ST + s*32768
constexpr int A_KH = 0, A_KL = 8192, A_VH = 16384, A_VL = 24576;
constexpr int SMEM_TOTAL = OFF_ST + 2 * 32768;   // 96 KB
}  // namespace

__device__ __align__(16) __nv_bfloat16 g_qh[NELEM], g_ql[NELEM];
__device__ __align__(16) __nv_bfloat16 g_kh[NELEM], g_kl[NELEM];
__device__ __align__(16) __nv_bfloat16 g_vh[NELEM], g_vl[NELEM];

__device__ __forceinline__ uint32_t swz256(uint32_t o) { return o ^ ((o >> 4) & 0x70); }
__device__ __forceinline__ uint32_t swz128(uint32_t o) { return o ^ ((o >> 3) & 0x70); }

__device__ __forceinline__ uint32_t smem_u32(const void* p) {
    uint32_t a;
    asm("{ .reg .u64 t; cvta.to.shared.u64 t, %1; cvt.u32.u64 %0, t; }" : "=r"(a) : "l"(p));
    return a;
}
__device__ __forceinline__ void ldsm_x4_t(uint32_t addr, uint32_t& r0, uint32_t& r1,
                                          uint32_t& r2, uint32_t& r3) {
    asm volatile("ldmatrix.sync.aligned.m8n8.x4.trans.shared.b16 {%0,%1,%2,%3}, [%4];"
                 : "=r"(r0), "=r"(r1), "=r"(r2), "=r"(r3) : "r"(addr));
}
__device__ __forceinline__ void ldsm_x4(uint32_t addr, uint32_t& r0, uint32_t& r1,
                                        uint32_t& r2, uint32_t& r3) {
    asm volatile("ldmatrix.sync.aligned.m8n8.x4.shared.b16 {%0,%1,%2,%3}, [%4];"
                 : "=r"(r0), "=r"(r1), "=r"(r2), "=r"(r3) : "r"(addr));
}
__device__ __forceinline__ void mma16816(float c[4], const uint32_t a[4],
                                         uint32_t b0, uint32_t b1) {
    asm volatile(
        "mma.sync.aligned.m16n8k16.row.col.f32.bf16.bf16.f32 "
        "{%0,%1,%2,%3}, {%4,%5,%6,%7}, {%8,%9}, {%0,%1,%2,%3};"
        : "+f"(c[0]), "+f"(c[1]), "+f"(c[2]), "+f"(c[3])
        : "r"(a[0]), "r"(a[1]), "r"(a[2]), "r"(a[3]), "r"(b0), "r"(b1));
}
__device__ __forceinline__ void split4(float4 f, uint2& h, uint2& l) {
    __nv_bfloat162 ha = __floats2bfloat162_rn(f.x, f.y);
    __nv_bfloat162 hb = __floats2bfloat162_rn(f.z, f.w);
    __nv_bfloat162 la = __floats2bfloat162_rn(f.x - __bfloat162float(ha.x),
                                              f.y - __bfloat162float(ha.y));
    __nv_bfloat162 lb = __floats2bfloat162_rn(f.z - __bfloat162float(hb.x),
                                              f.w - __bfloat162float(hb.y));
    h.x = *reinterpret_cast<uint32_t*>(&ha);
    h.y = *reinterpret_cast<uint32_t*>(&hb);
    l.x = *reinterpret_cast<uint32_t*>(&la);
    l.y = *reinterpret_cast<uint32_t*>(&lb);
}
__device__ __forceinline__ void pack_hl(float a, float b, uint32_t& h, uint32_t& l) {
    __nv_bfloat162 hh = __floats2bfloat162_rn(a, b);
    __nv_bfloat162 ll = __floats2bfloat162_rn(a - __bfloat162float(hh.x),
                                              b - __bfloat162float(hh.y));
    h = *reinterpret_cast<uint32_t*>(&hh);
    l = *reinterpret_cast<uint32_t*>(&ll);
}

#define CP_ASYNC16(dst, src) \
    asm volatile("cp.async.cg.shared.global [%0], [%1], 16;" :: "r"(dst), "l"(src) : "memory")
#define CP_COMMIT() asm volatile("cp.async.commit_group;" ::: "memory")
#define CP_WAIT1()  asm volatile("cp.async.wait_group 1;" ::: "memory")

// ---------------- pre-pass: fp32 -> bf16 hi/lo split ----------------
__global__ void convert_split(const float* __restrict__ q, const float* __restrict__ k,
                              const float* __restrict__ v) {
    const int NV4 = NELEM / 4;
    for (int i = blockIdx.x * blockDim.x + threadIdx.x; i < 3 * NV4;
         i += gridDim.x * blockDim.x) {
        const int t = i / NV4, j = i - t * NV4;
        const float* src = (t == 0) ? q : (t == 1) ? k : v;
        float4 f = reinterpret_cast<const float4*>(src)[j];
        if (t == 0) { f.x *= SCALE; f.y *= SCALE; f.z *= SCALE; f.w *= SCALE; }
        uint2 h, l;
        split4(f, h, l);
        __nv_bfloat16* dh = (t == 0) ? g_qh : (t == 1) ? g_kh : g_vh;
        __nv_bfloat16* dl = (t == 0) ? g_ql : (t == 1) ? g_kl : g_vl;
        reinterpret_cast<uint2*>(dh)[j] = h;
        reinterpret_cast<uint2*>(dl)[j] = l;
    }
}

// ---------------- main kernel ----------------
__device__ __forceinline__ void issue_tile(uint32_t sbase, size_t hbase, int kt, int tid) {
    const __nv_bfloat16* gsrc[4] = {g_kh, g_kl, g_vh, g_vl};
#pragma unroll
    for (int a = 0; a < 4; ++a) {
#pragma unroll
        for (int c = 0; c < 2; ++c) {
            const int ci = c * 256 + tid;        // 0..511 chunks of 16B
            const int d = ci >> 3, c8 = ci & 7;
            const void* src = gsrc[a] + hbase + (size_t)d * LEN + kt + c8 * 8;
            CP_ASYNC16(sbase + a * 8192 + swz128(d * 128 + c8 * 16), src);
        }
    }
}

__global__ void __launch_bounds__(256, 1)
attn_mma(float* __restrict__ outg) {
    extern __shared__ __align__(1024) char smem[];
    const uint32_t sb = smem_u32(smem);

    const int tid  = threadIdx.x;
    const int wid  = tid >> 5;
    const int lane = tid & 31;
    const int sub  = lane >> 3;
    const int li   = lane & 7;
    const int bh   = blockIdx.y;
    const int qt   = blockIdx.x * TQ;
    const size_t base = (size_t)bh * D * LEN;

    // prologue: async-load Q tile + tile0, then tile1
    {
        const __nv_bfloat16* gq[2] = {g_qh, g_ql};
#pragma unroll
        for (int a = 0; a < 2; ++a) {
#pragma unroll
            for (int c = 0; c < 4; ++c) {
                const int ci = c * 256 + tid;     // 0..1023 chunks
                const int d = ci >> 4, c16 = ci & 15;
                const void* src = gq[a] + base + (size_t)d * LEN + qt + c16 * 8;
                CP_ASYNC16(sb + (a ? OFF_QL : OFF_QH) + swz256(d * 256 + c16 * 16), src);
            }
        }
        issue_tile(sb + OFF_ST, base, 0, tid);
        CP_COMMIT();                              // G0 = Q + T0
        issue_tile(sb + OFF_ST + 32768, base, TK, tid);
        CP_COMMIT();                              // G1 = T1
    }
    CP_WAIT1();
    __syncthreads();

    // Q fragments (A of GEMM1): one-time ldsm
    uint32_t QHf[4][4], QLf[4][4];
    {
        const int q0 = wid * 16 + ((sub & 1) << 3);
#pragma unroll
        for (int j = 0; j < 4; ++j) {
            const int dr = 16 * j + ((sub >> 1) << 3) + li;
            ldsm_x4_t(sb + OFF_QH + swz256(dr * 256 + q0 * 2),
                      QHf[j][0], QHf[j][1], QHf[j][2], QHf[j][3]);
            ldsm_x4_t(sb + OFF_QL + swz256(dr * 256 + q0 * 2),
                      QLf[j][0], QLf[j][1], QLf[j][2], QLf[j][3]);
        }
    }

    float O[8][4];
#pragma unroll
    for (int n = 0; n < 8; ++n)
#pragma unroll
        for (int c = 0; c < 4; ++c) O[n][c] = 0.0f;
    float rsum0 = 0.0f, rsum1 = 0.0f;

    for (int t = 0; t < NT; ++t) {
        if (t) { CP_WAIT1(); __syncthreads(); }   // tile t landed
        const uint32_t stg = sb + OFF_ST + (t & 1) * 32768;

        // ---- GEMM1: S = Q·K^T (hi·hi + lo·hi + hi·lo) ----
        float S[8][4];
#pragma unroll
        for (int n = 0; n < 8; ++n)
#pragma unroll
            for (int c = 0; c < 4; ++c) S[n][c] = 0.0f;
#pragma unroll
        for (int j = 0; j < 4; ++j) {
            const int dr = 16 * j + ((sub & 1) << 3) + li;
#pragma unroll
            for (int np = 0; np < 4; ++np) {
                const int nc = 16 * np + ((sub >> 1) << 3);
                uint32_t b0, b1, b2, b3;
                ldsm_x4_t(stg + A_KH + swz128(dr * 128 + nc * 2), b0, b1, b2, b3);
                mma16816(S[2 * np],     QHf[j], b0, b1);
                mma16816(S[2 * np + 1], QHf[j], b2, b3);
                mma16816(S[2 * np],     QLf[j], b0, b1);
                mma16816(S[2 * np + 1], QLf[j], b2, b3);
                ldsm_x4_t(stg + A_KL + swz128(dr * 128 + nc * 2), b0, b1, b2, b3);
                mma16816(S[2 * np],     QHf[j], b0, b1);
                mma16816(S[2 * np + 1], QHf[j], b2, b3);
            }
        }

        // ---- leakyrelu + exp + row sums ----
        float t0 = 0.0f, t1 = 0.0f;
#pragma unroll
        for (int n = 0; n < 8; ++n) {
#pragma unroll
            for (int c = 0; c < 4; ++c) {
                float x = S[n][c];
                x = fmaxf(x, NSLOPE * x);
                S[n][c] = __expf(x);
            }
            t0 += S[n][0] + S[n][1];
            t1 += S[n][2] + S[n][3];
        }
        t0 += __shfl_xor_sync(0xffffffffu, t0, 1);
        t0 += __shfl_xor_sync(0xffffffffu, t0, 2);
        t1 += __shfl_xor_sync(0xffffffffu, t1, 1);
        t1 += __shfl_xor_sync(0xffffffffu, t1, 2);
        rsum0 += t0;
        rsum1 += t1;

        // ---- GEMM2: O += P·V^T, P repacked in-register ----
#pragma unroll
        for (int j = 0; j < 4; ++j) {
            uint32_t ah[4], al[4];
            pack_hl(S[2 * j][0],     S[2 * j][1],     ah[0], al[0]);
            pack_hl(S[2 * j][2],     S[2 * j][3],     ah[1], al[1]);
            pack_hl(S[2 * j + 1][0], S[2 * j + 1][1], ah[2], al[2]);
            pack_hl(S[2 * j + 1][2], S[2 * j + 1][3], ah[3], al[3]);
            const int kc = 16 * j + ((sub & 1) << 3);
#pragma unroll
            for (int dp = 0; dp < 4; ++dp) {
                const int dr = 16 * dp + ((sub >> 1) << 3) + li;
                uint32_t b0, b1, b2, b3;
                ldsm_x4(stg + A_VH + swz128(dr * 128 + kc * 2), b0, b1, b2, b3);
                mma16816(O[2 * dp],     ah, b0, b1);
                mma16816(O[2 * dp + 1], ah, b2, b3);
                mma16816(O[2 * dp],     al, b0, b1);
                mma16816(O[2 * dp + 1], al, b2, b3);
                ldsm_x4(stg + A_VL + swz128(dr * 128 + kc * 2), b0, b1, b2, b3);
                mma16816(O[2 * dp],     ah, b0, b1);
                mma16816(O[2 * dp + 1], ah, b2, b3);
            }
        }

        // ---- prefetch tile t+2 into the buffer we just finished ----
        if (t + 2 < NT) {
            __syncthreads();                      // everyone done reading stage t&1
            issue_tile(stg, base, (t + 2) * TK, tid);
        }
        CP_COMMIT();                              // uniform group count (may be empty)
    }

    // ---- normalize + store out[d][q] ----
    const float inv0 = 1.0f / rsum0;
    const float inv1 = 1.0f / rsum1;
    float* op = outg + base + qt + wid * 16 + (lane >> 2);
#pragma unroll
    for (int n = 0; n < 8; ++n) {
        const int d0 = 8 * n + 2 * (lane & 3);
        op[(size_t)d0 * LEN]           = O[n][0] * inv0;
        op[(size_t)(d0 + 1) * LEN]     = O[n][1] * inv0;
        op[(size_t)d0 * LEN + 8]       = O[n][2] * inv1;
        op[(size_t)(d0 + 1) * LEN + 8] = O[n][3] * inv1;
    }
}

extern "C" void kernel_launch(void* const* d_in, const int* in_sizes, int n_in,
                              void* d_out, int out_size) {
    const float* q = (const float*)d_in[0];
    const float* k = (const float*)d_in[1];
    const float* v = (const float*)d_in[2];
    float* out = (float*)d_out;

    convert_split<<<1024, 256>>>(q, k, v);

    cudaFuncSetAttribute(attn_mma, cudaFuncAttributeMaxDynamicSharedMemorySize, SMEM_TOTAL);
    dim3 grid(LEN / TQ, BH);                      // (16, 32) = 512 CTAs
    attn_mma<<<grid, 256, SMEM_TOTAL>>>(out);
}

// round 5
// speedup vs baseline: 4.6648x; 1.1456x over previous
#include <cuda_runtime.h>
#include <cuda_bf16.h>
#include <stdint.h>

// Attention_49194555408812: mma.sync bf16-split (3-pass fp32 emulation), sm_103-safe.
// Round 5: 128-thread CTAs (TQ=64, 2 CTAs/SM), 3-stage cp.async ring (1 barrier/tile),
// smem-staged coalesced output. Pre-pass converts Q(scaled)/K/V to bf16 hi/lo once.

namespace {
constexpr int D   = 64;
constexpr int LEN = 2048;
constexpr int BH  = 32;
constexpr int TQ  = 64;
constexpr int TK  = 64;
constexpr int NT  = LEN / TK;   // 32
constexpr float SCALE  = 0.125f;
constexpr float NSLOPE = 0.01f;
constexpr int NELEM = BH * D * LEN;

constexpr int OFF_QH = 0;                   // [d=64][q=64] bf16, 128B rows
constexpr int OFF_QL = 8192;
constexpr int OFF_ST = 16384;               // 3 stages x 32KB
constexpr int STAGE  = 32768;
constexpr int A_KH = 0, A_KL = 8192, A_VH = 16384, A_VL = 24576;
constexpr int SMEM_TOTAL = OFF_ST + 3 * STAGE;   // 114688 = 112 KB
constexpr int OPITCH = 68;                  // padded f32 pitch for output staging
}  // namespace

__device__ __align__(16) __nv_bfloat16 g_qh[NELEM], g_ql[NELEM];
__device__ __align__(16) __nv_bfloat16 g_kh[NELEM], g_kl[NELEM];
__device__ __align__(16) __nv_bfloat16 g_vh[NELEM], g_vl[NELEM];

__device__ __forceinline__ uint32_t swz128(uint32_t o) { return o ^ ((o >> 3) & 0x70); }

__device__ __forceinline__ uint32_t smem_u32(const void* p) {
    uint32_t a;
    asm("{ .reg .u64 t; cvta.to.shared.u64 t, %1; cvt.u32.u64 %0, t; }" : "=r"(a) : "l"(p));
    return a;
}
__device__ __forceinline__ void ldsm_x4_t(uint32_t addr, uint32_t& r0, uint32_t& r1,
                                          uint32_t& r2, uint32_t& r3) {
    asm volatile("ldmatrix.sync.aligned.m8n8.x4.trans.shared.b16 {%0,%1,%2,%3}, [%4];"
                 : "=r"(r0), "=r"(r1), "=r"(r2), "=r"(r3) : "r"(addr));
}
__device__ __forceinline__ void ldsm_x4(uint32_t addr, uint32_t& r0, uint32_t& r1,
                                        uint32_t& r2, uint32_t& r3) {
    asm volatile("ldmatrix.sync.aligned.m8n8.x4.shared.b16 {%0,%1,%2,%3}, [%4];"
                 : "=r"(r0), "=r"(r1), "=r"(r2), "=r"(r3) : "r"(addr));
}
__device__ __forceinline__ void mma16816(float c[4], const uint32_t a[4],
                                         uint32_t b0, uint32_t b1) {
    asm volatile(
        "mma.sync.aligned.m16n8k16.row.col.f32.bf16.bf16.f32 "
        "{%0,%1,%2,%3}, {%4,%5,%6,%7}, {%8,%9}, {%0,%1,%2,%3};"
        : "+f"(c[0]), "+f"(c[1]), "+f"(c[2]), "+f"(c[3])
        : "r"(a[0]), "r"(a[1]), "r"(a[2]), "r"(a[3]), "r"(b0), "r"(b1));
}
__device__ __forceinline__ void split4(float4 f, uint2& h, uint2& l) {
    __nv_bfloat162 ha = __floats2bfloat162_rn(f.x, f.y);
    __nv_bfloat162 hb = __floats2bfloat162_rn(f.z, f.w);
    __nv_bfloat162 la = __floats2bfloat162_rn(f.x - __bfloat162float(ha.x),
                                              f.y - __bfloat162float(ha.y));
    __nv_bfloat162 lb = __floats2bfloat162_rn(f.z - __bfloat162float(hb.x),
                                              f.w - __bfloat162float(hb.y));
    h.x = *reinterpret_cast<uint32_t*>(&ha);
    h.y = *reinterpret_cast<uint32_t*>(&hb);
    l.x = *reinterpret_cast<uint32_t*>(&la);
    l.y = *reinterpret_cast<uint32_t*>(&lb);
}
__device__ __forceinline__ void pack_hl(float a, float b, uint32_t& h, uint32_t& l) {
    __nv_bfloat162 hh = __floats2bfloat162_rn(a, b);
    __nv_bfloat162 ll = __floats2bfloat162_rn(a - __bfloat162float(hh.x),
                                              b - __bfloat162float(hh.y));
    h = *reinterpret_cast<uint32_t*>(&hh);
    l = *reinterpret_cast<uint32_t*>(&ll);
}

#define CP_ASYNC16(dst, src) \
    asm volatile("cp.async.cg.shared.global [%0], [%1], 16;" :: "r"(dst), "l"(src) : "memory")
#define CP_COMMIT() asm volatile("cp.async.commit_group;" ::: "memory")
#define CP_WAIT1()  asm volatile("cp.async.wait_group 1;" ::: "memory")

// ---------------- pre-pass: fp32 -> bf16 hi/lo split ----------------
__global__ void convert_split(const float* __restrict__ q, const float* __restrict__ k,
                              const float* __restrict__ v) {
    const int NV4 = NELEM / 4;
    for (int i = blockIdx.x * blockDim.x + threadIdx.x; i < 3 * NV4;
         i += gridDim.x * blockDim.x) {
        const int t = i / NV4, j = i - t * NV4;
        const float* src = (t == 0) ? q : (t == 1) ? k : v;
        float4 f = reinterpret_cast<const float4*>(src)[j];
        if (t == 0) { f.x *= SCALE; f.y *= SCALE; f.z *= SCALE; f.w *= SCALE; }
        uint2 h, l;
        split4(f, h, l);
        __nv_bfloat16* dh = (t == 0) ? g_qh : (t == 1) ? g_kh : g_vh;
        __nv_bfloat16* dl = (t == 0) ? g_ql : (t == 1) ? g_kl : g_vl;
        reinterpret_cast<uint2*>(dh)[j] = h;
        reinterpret_cast<uint2*>(dl)[j] = l;
    }
}

// ---------------- main kernel ----------------
__device__ __forceinline__ void issue_tile(uint32_t sbase, size_t hbase, int kt, int tid) {
    const __nv_bfloat16* gsrc[4] = {g_kh, g_kl, g_vh, g_vl};
#pragma unroll
    for (int a = 0; a < 4; ++a) {
#pragma unroll
        for (int c = 0; c < 4; ++c) {
            const int ci = c * 128 + tid;        // 0..511 chunks of 16B per array
            const int d = ci >> 3, c8 = ci & 7;
            const void* src = gsrc[a] + hbase + (size_t)d * LEN + kt + c8 * 8;
            CP_ASYNC16(sbase + a * 8192 + swz128(d * 128 + c8 * 16), src);
        }
    }
}

__global__ void __launch_bounds__(128, 2)
attn_mma(float* __restrict__ outg) {
    extern __shared__ __align__(1024) char smem[];
    const uint32_t sb = smem_u32(smem);

    const int tid  = threadIdx.x;
    const int wid  = tid >> 5;                 // 0..3
    const int lane = tid & 31;
    const int sub  = lane >> 3;
    const int li   = lane & 7;
    const int bh   = blockIdx.y;
    const int qt   = blockIdx.x * TQ;
    const size_t base = (size_t)bh * D * LEN;

    // prologue: Q (hi+lo) + tile0 as group0; tile1 as group1
    {
        const __nv_bfloat16* gq[2] = {g_qh, g_ql};
#pragma unroll
        for (int a = 0; a < 2; ++a) {
#pragma unroll
            for (int c = 0; c < 4; ++c) {
                const int ci = c * 128 + tid;   // 512 chunks per buffer
                const int d = ci >> 3, c8 = ci & 7;
                const void* src = gq[a] + base + (size_t)d * LEN + qt + c8 * 8;
                CP_ASYNC16(sb + (a ? OFF_QL : OFF_QH) + swz128(d * 128 + c8 * 16), src);
            }
        }
        issue_tile(sb + OFF_ST, base, 0, tid);
        CP_COMMIT();
        issue_tile(sb + OFF_ST + STAGE, base, TK, tid);
        CP_COMMIT();
    }
    CP_WAIT1();
    __syncthreads();

    // Q fragments (one-time)
    uint32_t QHf[4][4], QLf[4][4];
    {
        const int q0 = wid * 16 + ((sub & 1) << 3);
#pragma unroll
        for (int j = 0; j < 4; ++j) {
            const int dr = 16 * j + ((sub >> 1) << 3) + li;
            ldsm_x4_t(sb + OFF_QH + swz128(dr * 128 + q0 * 2),
                      QHf[j][0], QHf[j][1], QHf[j][2], QHf[j][3]);
            ldsm_x4_t(sb + OFF_QL + swz128(dr * 128 + q0 * 2),
                      QLf[j][0], QLf[j][1], QLf[j][2], QLf[j][3]);
        }
    }

    float O[8][4];
#pragma unroll
    for (int n = 0; n < 8; ++n)
#pragma unroll
        for (int c = 0; c < 4; ++c) O[n][c] = 0.0f;
    float rsum0 = 0.0f, rsum1 = 0.0f;

    int stg_idx = 0;
    for (int t = 0; t < NT; ++t) {
        if (t) { CP_WAIT1(); __syncthreads(); }
        const uint32_t stg = sb + OFF_ST + stg_idx * STAGE;

        // ---- GEMM1: S = Q·K^T (hi·hi + lo·hi + hi·lo) ----
        float S[8][4];
#pragma unroll
        for (int n = 0; n < 8; ++n)
#pragma unroll
            for (int c = 0; c < 4; ++c) S[n][c] = 0.0f;
#pragma unroll
        for (int j = 0; j < 4; ++j) {
            const int dr = 16 * j + ((sub & 1) << 3) + li;
#pragma unroll
            for (int np = 0; np < 4; ++np) {
                const int nc = 16 * np + ((sub >> 1) << 3);
                uint32_t b0, b1, b2, b3;
                ldsm_x4_t(stg + A_KH + swz128(dr * 128 + nc * 2), b0, b1, b2, b3);
                mma16816(S[2 * np],     QHf[j], b0, b1);
                mma16816(S[2 * np + 1], QHf[j], b2, b3);
                mma16816(S[2 * np],     QLf[j], b0, b1);
                mma16816(S[2 * np + 1], QLf[j], b2, b3);
                ldsm_x4_t(stg + A_KL + swz128(dr * 128 + nc * 2), b0, b1, b2, b3);
                mma16816(S[2 * np],     QHf[j], b0, b1);
                mma16816(S[2 * np + 1], QHf[j], b2, b3);
            }
        }

        // ---- leakyrelu + exp + row sums ----
        float t0 = 0.0f, t1 = 0.0f;
#pragma unroll
        for (int n = 0; n < 8; ++n) {
#pragma unroll
            for (int c = 0; c < 4; ++c) {
                float x = S[n][c];
                x = fmaxf(x, NSLOPE * x);
                S[n][c] = __expf(x);
            }
            t0 += S[n][0] + S[n][1];
            t1 += S[n][2] + S[n][3];
        }
        t0 += __shfl_xor_sync(0xffffffffu, t0, 1);
        t0 += __shfl_xor_sync(0xffffffffu, t0, 2);
        t1 += __shfl_xor_sync(0xffffffffu, t1, 1);
        t1 += __shfl_xor_sync(0xffffffffu, t1, 2);
        rsum0 += t0;
        rsum1 += t1;

        // ---- GEMM2: O += P·V^T (in-register repack) ----
#pragma unroll
        for (int j = 0; j < 4; ++j) {
            uint32_t ah[4], al[4];
            pack_hl(S[2 * j][0],     S[2 * j][1],     ah[0], al[0]);
            pack_hl(S[2 * j][2],     S[2 * j][3],     ah[1], al[1]);
            pack_hl(S[2 * j + 1][0], S[2 * j + 1][1], ah[2], al[2]);
            pack_hl(S[2 * j + 1][2], S[2 * j + 1][3], ah[3], al[3]);
            const int kc = 16 * j + ((sub & 1) << 3);
#pragma unroll
            for (int dp = 0; dp < 4; ++dp) {
                const int dr = 16 * dp + ((sub >> 1) << 3) + li;
                uint32_t b0, b1, b2, b3;
                ldsm_x4(stg + A_VH + swz128(dr * 128 + kc * 2), b0, b1, b2, b3);
                mma16816(O[2 * dp],     ah, b0, b1);
                mma16816(O[2 * dp + 1], ah, b2, b3);
                mma16816(O[2 * dp],     al, b0, b1);
                mma16816(O[2 * dp + 1], al, b2, b3);
                ldsm_x4(stg + A_VL + swz128(dr * 128 + kc * 2), b0, b1, b2, b3);
                mma16816(O[2 * dp],     ah, b0, b1);
                mma16816(O[2 * dp + 1], ah, b2, b3);
            }
        }

        // ---- prefetch t+2 into the stage last read at tile t-1 ----
        if (t + 2 < NT)
            issue_tile(sb + OFF_ST + ((stg_idx + 2) % 3) * STAGE, base, (t + 2) * TK, tid);
        CP_COMMIT();                              // uniform group count
        stg_idx = (stg_idx + 1) % 3;
    }

    // ---- epilogue: stage O in smem (padded pitch), coalesced float4 stores ----
    __syncthreads();                              // all reads of stage 0 region done
    float* Obuf = reinterpret_cast<float*>(smem + OFF_ST);
    const float inv0 = 1.0f / rsum0;
    const float inv1 = 1.0f / rsum1;
    const int qc = wid * 16 + (lane >> 2);
#pragma unroll
    for (int n = 0; n < 8; ++n) {
        const int d0 = 8 * n + 2 * (lane & 3);
        Obuf[d0 * OPITCH + qc]           = O[n][0] * inv0;
        Obuf[(d0 + 1) * OPITCH + qc]     = O[n][1] * inv0;
        Obuf[d0 * OPITCH + qc + 8]       = O[n][2] * inv1;
        Obuf[(d0 + 1) * OPITCH + qc + 8] = O[n][3] * inv1;
    }
    __syncthreads();
#pragma unroll
    for (int i = 0; i < 8; ++i) {
        const int idx = i * 128 + tid;            // 1024 float4 total
        const int row = idx >> 4, c4 = idx & 15;
        float4 val = *reinterpret_cast<const float4*>(Obuf + row * OPITCH + c4 * 4);
        *reinterpret_cast<float4*>(outg + base + (size_t)row * LEN + qt + c4 * 4) = val;
    }
}

extern "C" void kernel_launch(void* const* d_in, const int* in_sizes, int n_in,
                              void* d_out, int out_size) {
    const float* q = (const float*)d_in[0];
    const float* k = (const float*)d_in[1];
    const float* v = (const float*)d_in[2];
    float* out = (float*)d_out;

    convert_split<<<1024, 256>>>(q, k, v);

    cudaFuncSetAttribute(attn_mma, cudaFuncAttributeMaxDynamicSharedMemorySize, SMEM_TOTAL);
    dim3 grid(LEN / TQ, BH);                      // (32, 32) = 1024 CTAs
    attn_mma<<<grid, 128, SMEM_TOTAL>>>(out);
}

// round 6
// speedup vs baseline: 6.3304x; 1.3570x over previous
#include <cuda_runtime.h>
#include <cuda_fp16.h>
#include <stdint.h>

// Attention_49194555408812: mma.sync fp16 2-pass split (A-side hi/lo), sm_103-safe.
// Round 6: K/V stored as plain fp16 (dropped B-side residual ~2^-11); Q and P split
// hi/lo. 3 CTAs/SM (64KB smem, 128 thr), 3-stage cp.async ring, coalesced epilogue.

namespace {
constexpr int D   = 64;
constexpr int LEN = 2048;
constexpr int BH  = 32;
constexpr int TQ  = 64;
constexpr int TK  = 64;
constexpr int NT  = LEN / TK;   // 32
constexpr float SCALE  = 0.125f;
constexpr float NSLOPE = 0.01f;
constexpr int NELEM = BH * D * LEN;

constexpr int OFF_QH = 0;                   // [d=64][q=64] fp16, 128B rows
constexpr int OFF_QL = 8192;
constexpr int OFF_ST = 16384;               // 3 stages x 16KB
constexpr int STAGE  = 16384;
constexpr int A_KH = 0, A_VH = 8192;
constexpr int SMEM_TOTAL = OFF_ST + 3 * STAGE;   // 65536 = 64 KB
constexpr int OPITCH = 68;
}  // namespace

__device__ __align__(16) __half g_qh[NELEM], g_ql[NELEM];
__device__ __align__(16) __half g_k[NELEM], g_v[NELEM];

__device__ __forceinline__ uint32_t swz128(uint32_t o) { return o ^ ((o >> 3) & 0x70); }

__device__ __forceinline__ uint32_t smem_u32(const void* p) {
    uint32_t a;
    asm("{ .reg .u64 t; cvta.to.shared.u64 t, %1; cvt.u32.u64 %0, t; }" : "=r"(a) : "l"(p));
    return a;
}
__device__ __forceinline__ void ldsm_x4_t(uint32_t addr, uint32_t& r0, uint32_t& r1,
                                          uint32_t& r2, uint32_t& r3) {
    asm volatile("ldmatrix.sync.aligned.m8n8.x4.trans.shared.b16 {%0,%1,%2,%3}, [%4];"
                 : "=r"(r0), "=r"(r1), "=r"(r2), "=r"(r3) : "r"(addr));
}
__device__ __forceinline__ void ldsm_x4(uint32_t addr, uint32_t& r0, uint32_t& r1,
                                        uint32_t& r2, uint32_t& r3) {
    asm volatile("ldmatrix.sync.aligned.m8n8.x4.shared.b16 {%0,%1,%2,%3}, [%4];"
                 : "=r"(r0), "=r"(r1), "=r"(r2), "=r"(r3) : "r"(addr));
}
__device__ __forceinline__ void mma16816(float c[4], const uint32_t a[4],
                                         uint32_t b0, uint32_t b1) {
    asm volatile(
        "mma.sync.aligned.m16n8k16.row.col.f32.f16.f16.f32 "
        "{%0,%1,%2,%3}, {%4,%5,%6,%7}, {%8,%9}, {%0,%1,%2,%3};"
        : "+f"(c[0]), "+f"(c[1]), "+f"(c[2]), "+f"(c[3])
        : "r"(a[0]), "r"(a[1]), "r"(a[2]), "r"(a[3]), "r"(b0), "r"(b1));
}
__device__ __forceinline__ uint32_t h2_bits(float a, float b) {
    __half2 h = __floats2half2_rn(a, b);
    return *reinterpret_cast<uint32_t*>(&h);
}
// fp16 hi + residual lo for a float pair
__device__ __forceinline__ void pack_hl(float a, float b, uint32_t& h, uint32_t& l) {
    __half2 hh = __floats2half2_rn(a, b);
    float2 hf = __half22float2(hh);
    __half2 ll = __floats2half2_rn(a - hf.x, b - hf.y);
    h = *reinterpret_cast<uint32_t*>(&hh);
    l = *reinterpret_cast<uint32_t*>(&ll);
}

#define CP_ASYNC16(dst, src) \
    asm volatile("cp.async.cg.shared.global [%0], [%1], 16;" :: "r"(dst), "l"(src) : "memory")
#define CP_COMMIT() asm volatile("cp.async.commit_group;" ::: "memory")
#define CP_WAIT1()  asm volatile("cp.async.wait_group 1;" ::: "memory")

// ---------------- pre-pass: Q -> fp16 hi/lo (scaled); K,V -> fp16 ----------------
__global__ void convert_split(const float* __restrict__ q, const float* __restrict__ k,
                              const float* __restrict__ v) {
    const int NV4 = NELEM / 4;
    for (int i = blockIdx.x * blockDim.x + threadIdx.x; i < 3 * NV4;
         i += gridDim.x * blockDim.x) {
        const int t = i / NV4, j = i - t * NV4;
        if (t == 0) {
            float4 f = reinterpret_cast<const float4*>(q)[j];
            f.x *= SCALE; f.y *= SCALE; f.z *= SCALE; f.w *= SCALE;
            uint32_t h0, l0, h1, l1;
            pack_hl(f.x, f.y, h0, l0);
            pack_hl(f.z, f.w, h1, l1);
            reinterpret_cast<uint2*>(g_qh)[j] = make_uint2(h0, h1);
            reinterpret_cast<uint2*>(g_ql)[j] = make_uint2(l0, l1);
        } else {
            const float* src = (t == 1) ? k : v;
            __half* dst = (t == 1) ? g_k : g_v;
            float4 f = reinterpret_cast<const float4*>(src)[j];
            reinterpret_cast<uint2*>(dst)[j] =
                make_uint2(h2_bits(f.x, f.y), h2_bits(f.z, f.w));
        }
    }
}

// ---------------- main kernel ----------------
__device__ __forceinline__ void issue_tile(uint32_t sbase, size_t hbase, int kt, int tid) {
    const __half* gsrc[2] = {g_k, g_v};
#pragma unroll
    for (int a = 0; a < 2; ++a) {
#pragma unroll
        for (int c = 0; c < 4; ++c) {
            const int ci = c * 128 + tid;        // 0..511 chunks of 16B per array
            const int d = ci >> 3, c8 = ci & 7;
            const void* src = gsrc[a] + hbase + (size_t)d * LEN + kt + c8 * 8;
            CP_ASYNC16(sbase + a * 8192 + swz128(d * 128 + c8 * 16), src);
        }
    }
}

__global__ void __launch_bounds__(128, 3)
attn_mma(float* __restrict__ outg) {
    extern __shared__ __align__(1024) char smem[];
    const uint32_t sb = smem_u32(smem);

    const int tid  = threadIdx.x;
    const int wid  = tid >> 5;
    const int lane = tid & 31;
    const int sub  = lane >> 3;
    const int li   = lane & 7;
    const int bh   = blockIdx.y;
    const int qt   = blockIdx.x * TQ;
    const size_t base = (size_t)bh * D * LEN;

    // prologue: Q hi/lo + tile0 as group0; tile1 as group1
    {
        const __half* gq[2] = {g_qh, g_ql};
#pragma unroll
        for (int a = 0; a < 2; ++a) {
#pragma unroll
            for (int c = 0; c < 4; ++c) {
                const int ci = c * 128 + tid;
                const int d = ci >> 3, c8 = ci & 7;
                const void* src = gq[a] + base + (size_t)d * LEN + qt + c8 * 8;
                CP_ASYNC16(sb + (a ? OFF_QL : OFF_QH) + swz128(d * 128 + c8 * 16), src);
            }
        }
        issue_tile(sb + OFF_ST, base, 0, tid);
        CP_COMMIT();
        issue_tile(sb + OFF_ST + STAGE, base, TK, tid);
        CP_COMMIT();
    }
    CP_WAIT1();
    __syncthreads();

    // Q fragments (one-time)
    uint32_t QHf[4][4], QLf[4][4];
    {
        const int q0 = wid * 16 + ((sub & 1) << 3);
#pragma unroll
        for (int j = 0; j < 4; ++j) {
            const int dr = 16 * j + ((sub >> 1) << 3) + li;
            ldsm_x4_t(sb + OFF_QH + swz128(dr * 128 + q0 * 2),
                      QHf[j][0], QHf[j][1], QHf[j][2], QHf[j][3]);
            ldsm_x4_t(sb + OFF_QL + swz128(dr * 128 + q0 * 2),
                      QLf[j][0], QLf[j][1], QLf[j][2], QLf[j][3]);
        }
    }

    float O[8][4];
#pragma unroll
    for (int n = 0; n < 8; ++n)
#pragma unroll
        for (int c = 0; c < 4; ++c) O[n][c] = 0.0f;
    float rsum0 = 0.0f, rsum1 = 0.0f;

    int stg_idx = 0;
    for (int t = 0; t < NT; ++t) {
        if (t) { CP_WAIT1(); __syncthreads(); }
        const uint32_t stg = sb + OFF_ST + stg_idx * STAGE;

        // ---- GEMM1: S = Qh·K + Ql·K ----
        float S[8][4];
#pragma unroll
        for (int n = 0; n < 8; ++n)
#pragma unroll
            for (int c = 0; c < 4; ++c) S[n][c] = 0.0f;
#pragma unroll
        for (int j = 0; j < 4; ++j) {
            const int dr = 16 * j + ((sub & 1) << 3) + li;
#pragma unroll
            for (int np = 0; np < 4; ++np) {
                const int nc = 16 * np + ((sub >> 1) << 3);
                uint32_t b0, b1, b2, b3;
                ldsm_x4_t(stg + A_KH + swz128(dr * 128 + nc * 2), b0, b1, b2, b3);
                mma16816(S[2 * np],     QHf[j], b0, b1);
                mma16816(S[2 * np + 1], QHf[j], b2, b3);
                mma16816(S[2 * np],     QLf[j], b0, b1);
                mma16816(S[2 * np + 1], QLf[j], b2, b3);
            }
        }

        // ---- leakyrelu + exp + row sums ----
        float t0 = 0.0f, t1 = 0.0f;
#pragma unroll
        for (int n = 0; n < 8; ++n) {
#pragma unroll
            for (int c = 0; c < 4; ++c) {
                float x = S[n][c];
                x = fmaxf(x, NSLOPE * x);
                S[n][c] = __expf(x);
            }
            t0 += S[n][0] + S[n][1];
            t1 += S[n][2] + S[n][3];
        }
        t0 += __shfl_xor_sync(0xffffffffu, t0, 1);
        t0 += __shfl_xor_sync(0xffffffffu, t0, 2);
        t1 += __shfl_xor_sync(0xffffffffu, t1, 1);
        t1 += __shfl_xor_sync(0xffffffffu, t1, 2);
        rsum0 += t0;
        rsum1 += t1;

        // ---- GEMM2: O += Ph·V + Pl·V (in-register repack) ----
#pragma unroll
        for (int j = 0; j < 4; ++j) {
            uint32_t ah[4], al[4];
            pack_hl(S[2 * j][0],     S[2 * j][1],     ah[0], al[0]);
            pack_hl(S[2 * j][2],     S[2 * j][3],     ah[1], al[1]);
            pack_hl(S[2 * j + 1][0], S[2 * j + 1][1], ah[2], al[2]);
            pack_hl(S[2 * j + 1][2], S[2 * j + 1][3], ah[3], al[3]);
            const int kc = 16 * j + ((sub & 1) << 3);
#pragma unroll
            for (int dp = 0; dp < 4; ++dp) {
                const int dr = 16 * dp + ((sub >> 1) << 3) + li;
                uint32_t b0, b1, b2, b3;
                ldsm_x4(stg + A_VH + swz128(dr * 128 + kc * 2), b0, b1, b2, b3);
                mma16816(O[2 * dp],     ah, b0, b1);
                mma16816(O[2 * dp + 1], ah, b2, b3);
                mma16816(O[2 * dp],     al, b0, b1);
                mma16816(O[2 * dp + 1], al, b2, b3);
            }
        }

        // ---- prefetch t+2 into the stage last read at tile t-1 ----
        if (t + 2 < NT)
            issue_tile(sb + OFF_ST + ((stg_idx + 2) % 3) * STAGE, base, (t + 2) * TK, tid);
        CP_COMMIT();
        stg_idx = (stg_idx + 1) % 3;
    }

    // ---- epilogue: stage O in smem (padded pitch), coalesced float4 stores ----
    __syncthreads();
    float* Obuf = reinterpret_cast<float*>(smem + OFF_ST);
    const float inv0 = 1.0f / rsum0;
    const float inv1 = 1.0f / rsum1;
    const int qc = wid * 16 + (lane >> 2);
#pragma unroll
    for (int n = 0; n < 8; ++n) {
        const int d0 = 8 * n + 2 * (lane & 3);
        Obuf[d0 * OPITCH + qc]           = O[n][0] * inv0;
        Obuf[(d0 + 1) * OPITCH + qc]     = O[n][1] * inv0;
        Obuf[d0 * OPITCH + qc + 8]       = O[n][2] * inv1;
        Obuf[(d0 + 1) * OPITCH + qc + 8] = O[n][3] * inv1;
    }
    __syncthreads();
#pragma unroll
    for (int i = 0; i < 8; ++i) {
        const int idx = i * 128 + tid;
        const int row = idx >> 4, c4 = idx & 15;
        float4 val = *reinterpret_cast<const float4*>(Obuf + row * OPITCH + c4 * 4);
        *reinterpret_cast<float4*>(outg + base + (size_t)row * LEN + qt + c4 * 4) = val;
    }
}

extern "C" void kernel_launch(void* const* d_in, const int* in_sizes, int n_in,
                              void* d_out, int out_size) {
    const float* q = (const float*)d_in[0];
    const float* k = (const float*)d_in[1];
    const float* v = (const float*)d_in[2];
    float* out = (float*)d_out;

    convert_split<<<1024, 256>>>(q, k, v);

    cudaFuncSetAttribute(attn_mma, cudaFuncAttributeMaxDynamicSharedMemorySize, SMEM_TOTAL);
    dim3 grid(LEN / TQ, BH);                      // (32, 32) = 1024 CTAs
    attn_mma<<<grid, 128, SMEM_TOTAL>>>(out);
}

// round 7
// speedup vs baseline: 8.1590x; 1.2889x over previous
#include <cuda_runtime.h>
#include <cuda_fp16.h>
#include <stdint.h>

// Attention_49194555408812: mma.sync fp16, sm_103-safe.
// Round 7: GEMM1 2-pass (Qh+Ql), GEMM2 single-pass (P fp16, ~3e-4 budgeted);
// exp2-folded softmax (Q pre-scaled by 1/8*log2e), deferred rsum reduction,
// prefetch hoisted. 3 CTAs/SM, 3-stage cp.async ring, coalesced epilogue.

namespace {
constexpr int D   = 64;
constexpr int LEN = 2048;
constexpr int BH  = 32;
constexpr int TQ  = 64;
constexpr int TK  = 64;
constexpr int NT  = LEN / TK;   // 32
constexpr float QSCALE = 0.125f * 1.4426950408889634f;   // 1/sqrt(64) * log2(e)
constexpr float NSLOPE = 0.01f;
constexpr int NELEM = BH * D * LEN;

constexpr int OFF_QH = 0;                   // [d=64][q=64] fp16, 128B rows
constexpr int OFF_QL = 8192;
constexpr int OFF_ST = 16384;               // 3 stages x 16KB
constexpr int STAGE  = 16384;
constexpr int A_KH = 0, A_VH = 8192;
constexpr int SMEM_TOTAL = OFF_ST + 3 * STAGE;   // 64 KB
constexpr int OPITCH = 68;
}  // namespace

__device__ __align__(16) __half g_qh[NELEM], g_ql[NELEM];
__device__ __align__(16) __half g_k[NELEM], g_v[NELEM];

__device__ __forceinline__ uint32_t swz128(uint32_t o) { return o ^ ((o >> 3) & 0x70); }

__device__ __forceinline__ uint32_t smem_u32(const void* p) {
    uint32_t a;
    asm("{ .reg .u64 t; cvta.to.shared.u64 t, %1; cvt.u32.u64 %0, t; }" : "=r"(a) : "l"(p));
    return a;
}
__device__ __forceinline__ void ldsm_x4_t(uint32_t addr, uint32_t& r0, uint32_t& r1,
                                          uint32_t& r2, uint32_t& r3) {
    asm volatile("ldmatrix.sync.aligned.m8n8.x4.trans.shared.b16 {%0,%1,%2,%3}, [%4];"
                 : "=r"(r0), "=r"(r1), "=r"(r2), "=r"(r3) : "r"(addr));
}
__device__ __forceinline__ void ldsm_x4(uint32_t addr, uint32_t& r0, uint32_t& r1,
                                        uint32_t& r2, uint32_t& r3) {
    asm volatile("ldmatrix.sync.aligned.m8n8.x4.shared.b16 {%0,%1,%2,%3}, [%4];"
                 : "=r"(r0), "=r"(r1), "=r"(r2), "=r"(r3) : "r"(addr));
}
__device__ __forceinline__ void mma16816(float c[4], const uint32_t a[4],
                                         uint32_t b0, uint32_t b1) {
    asm volatile(
        "mma.sync.aligned.m16n8k16.row.col.f32.f16.f16.f32 "
        "{%0,%1,%2,%3}, {%4,%5,%6,%7}, {%8,%9}, {%0,%1,%2,%3};"
        : "+f"(c[0]), "+f"(c[1]), "+f"(c[2]), "+f"(c[3])
        : "r"(a[0]), "r"(a[1]), "r"(a[2]), "r"(a[3]), "r"(b0), "r"(b1));
}
__device__ __forceinline__ uint32_t h2_bits(float a, float b) {
    __half2 h = __floats2half2_rn(a, b);
    return *reinterpret_cast<uint32_t*>(&h);
}
__device__ __forceinline__ void pack_hl(float a, float b, uint32_t& h, uint32_t& l) {
    __half2 hh = __floats2half2_rn(a, b);
    float2 hf = __half22float2(hh);
    __half2 ll = __floats2half2_rn(a - hf.x, b - hf.y);
    h = *reinterpret_cast<uint32_t*>(&hh);
    l = *reinterpret_cast<uint32_t*>(&ll);
}
__device__ __forceinline__ float ex2(float x) {
    float y;
    asm("ex2.approx.f32 %0, %1;" : "=f"(y) : "f"(x));
    return y;
}

#define CP_ASYNC16(dst, src) \
    asm volatile("cp.async.cg.shared.global [%0], [%1], 16;" :: "r"(dst), "l"(src) : "memory")
#define CP_COMMIT() asm volatile("cp.async.commit_group;" ::: "memory")
#define CP_WAIT1()  asm volatile("cp.async.wait_group 1;" ::: "memory")

// ---------------- pre-pass: Q -> fp16 hi/lo (scaled by 1/8*log2e); K,V -> fp16 ----
__global__ void convert_split(const float* __restrict__ q, const float* __restrict__ k,
                              const float* __restrict__ v) {
    const int NV4 = NELEM / 4;
    for (int i = blockIdx.x * blockDim.x + threadIdx.x; i < 3 * NV4;
         i += gridDim.x * blockDim.x) {
        const int t = i / NV4, j = i - t * NV4;
        if (t == 0) {
            float4 f = reinterpret_cast<const float4*>(q)[j];
            f.x *= QSCALE; f.y *= QSCALE; f.z *= QSCALE; f.w *= QSCALE;
            uint32_t h0, l0, h1, l1;
            pack_hl(f.x, f.y, h0, l0);
            pack_hl(f.z, f.w, h1, l1);
            reinterpret_cast<uint2*>(g_qh)[j] = make_uint2(h0, h1);
            reinterpret_cast<uint2*>(g_ql)[j] = make_uint2(l0, l1);
        } else {
            const float* src = (t == 1) ? k : v;
            __half* dst = (t == 1) ? g_k : g_v;
            float4 f = reinterpret_cast<const float4*>(src)[j];
            reinterpret_cast<uint2*>(dst)[j] =
                make_uint2(h2_bits(f.x, f.y), h2_bits(f.z, f.w));
        }
    }
}

// ---------------- main kernel ----------------
__device__ __forceinline__ void issue_tile(uint32_t sbase, size_t hbase, int kt, int tid) {
    const __half* gsrc[2] = {g_k, g_v};
#pragma unroll
    for (int a = 0; a < 2; ++a) {
#pragma unroll
        for (int c = 0; c < 4; ++c) {
            const int ci = c * 128 + tid;        // 512 chunks of 16B per array
            const int d = ci >> 3, c8 = ci & 7;
            const void* src = gsrc[a] + hbase + (size_t)d * LEN + kt + c8 * 8;
            CP_ASYNC16(sbase + a * 8192 + swz128(d * 128 + c8 * 16), src);
        }
    }
}

__global__ void __launch_bounds__(128, 3)
attn_mma(float* __restrict__ outg) {
    extern __shared__ __align__(1024) char smem[];
    const uint32_t sb = smem_u32(smem);

    const int tid  = threadIdx.x;
    const int wid  = tid >> 5;
    const int lane = tid & 31;
    const int sub  = lane >> 3;
    const int li   = lane & 7;
    const int bh   = blockIdx.y;
    const int qt   = blockIdx.x * TQ;
    const size_t base = (size_t)bh * D * LEN;

    // prologue: Q hi/lo + tile0 as group0; tile1 as group1
    {
        const __half* gq[2] = {g_qh, g_ql};
#pragma unroll
        for (int a = 0; a < 2; ++a) {
#pragma unroll
            for (int c = 0; c < 4; ++c) {
                const int ci = c * 128 + tid;
                const int d = ci >> 3, c8 = ci & 7;
                const void* src = gq[a] + base + (size_t)d * LEN + qt + c8 * 8;
                CP_ASYNC16(sb + (a ? OFF_QL : OFF_QH) + swz128(d * 128 + c8 * 16), src);
            }
        }
        issue_tile(sb + OFF_ST, base, 0, tid);
        CP_COMMIT();
        issue_tile(sb + OFF_ST + STAGE, base, TK, tid);
        CP_COMMIT();
    }
    CP_WAIT1();
    __syncthreads();

    // Q fragments (one-time)
    uint32_t QHf[4][4], QLf[4][4];
    {
        const int q0 = wid * 16 + ((sub & 1) << 3);
#pragma unroll
        for (int j = 0; j < 4; ++j) {
            const int dr = 16 * j + ((sub >> 1) << 3) + li;
            ldsm_x4_t(sb + OFF_QH + swz128(dr * 128 + q0 * 2),
                      QHf[j][0], QHf[j][1], QHf[j][2], QHf[j][3]);
            ldsm_x4_t(sb + OFF_QL + swz128(dr * 128 + q0 * 2),
                      QLf[j][0], QLf[j][1], QLf[j][2], QLf[j][3]);
        }
    }

    float O[8][4];
#pragma unroll
    for (int n = 0; n < 8; ++n)
#pragma unroll
        for (int c = 0; c < 4; ++c) O[n][c] = 0.0f;
    float rsum0 = 0.0f, rsum1 = 0.0f;   // per-thread partials (quad-reduced at end)

    int stg_idx = 0;
    for (int t = 0; t < NT; ++t) {
        if (t) { CP_WAIT1(); __syncthreads(); }
        const uint32_t stg = sb + OFF_ST + stg_idx * STAGE;

        // prefetch t+2 into the stage last read at t-1 (protected by barrier above)
        if (t + 2 < NT)
            issue_tile(sb + OFF_ST + ((stg_idx + 2) % 3) * STAGE, base, (t + 2) * TK, tid);
        CP_COMMIT();                              // uniform group count

        // ---- GEMM1: S' = (Qh + Ql)·K  (log2e-scaled scores) ----
        float S[8][4];
#pragma unroll
        for (int n = 0; n < 8; ++n)
#pragma unroll
            for (int c = 0; c < 4; ++c) S[n][c] = 0.0f;
#pragma unroll
        for (int j = 0; j < 4; ++j) {
            const int dr = 16 * j + ((sub & 1) << 3) + li;
#pragma unroll
            for (int np = 0; np < 4; ++np) {
                const int nc = 16 * np + ((sub >> 1) << 3);
                uint32_t b0, b1, b2, b3;
                ldsm_x4_t(stg + A_KH + swz128(dr * 128 + nc * 2), b0, b1, b2, b3);
                mma16816(S[2 * np],     QHf[j], b0, b1);
                mma16816(S[2 * np + 1], QHf[j], b2, b3);
                mma16816(S[2 * np],     QLf[j], b0, b1);
                mma16816(S[2 * np + 1], QLf[j], b2, b3);
            }
        }

        // ---- p = 2^(leakyrelu(s'));  accumulate per-thread partial sums ----
        float t0 = 0.0f, t1 = 0.0f;
#pragma unroll
        for (int n = 0; n < 8; ++n) {
#pragma unroll
            for (int c = 0; c < 4; ++c) {
                float x = S[n][c];
                S[n][c] = ex2(fmaxf(x, NSLOPE * x));
            }
            t0 += S[n][0] + S[n][1];
            t1 += S[n][2] + S[n][3];
        }
        rsum0 += t0;
        rsum1 += t1;

        // ---- GEMM2: O += P·V (single fp16 pass, in-register repack) ----
#pragma unroll
        for (int j = 0; j < 4; ++j) {
            uint32_t ah[4];
            ah[0] = h2_bits(S[2 * j][0],     S[2 * j][1]);
            ah[1] = h2_bits(S[2 * j][2],     S[2 * j][3]);
            ah[2] = h2_bits(S[2 * j + 1][0], S[2 * j + 1][1]);
            ah[3] = h2_bits(S[2 * j + 1][2], S[2 * j + 1][3]);
            const int kc = 16 * j + ((sub & 1) << 3);
#pragma unroll
            for (int dp = 0; dp < 4; ++dp) {
                const int dr = 16 * dp + ((sub >> 1) << 3) + li;
                uint32_t b0, b1, b2, b3;
                ldsm_x4(stg + A_VH + swz128(dr * 128 + kc * 2), b0, b1, b2, b3);
                mma16816(O[2 * dp],     ah, b0, b1);
                mma16816(O[2 * dp + 1], ah, b2, b3);
            }
        }

        stg_idx = (stg_idx + 1) % 3;
    }

    // ---- deferred quad reduction of row sums (lanes differing in bits 0..1) ----
    rsum0 += __shfl_xor_sync(0xffffffffu, rsum0, 1);
    rsum0 += __shfl_xor_sync(0xffffffffu, rsum0, 2);
    rsum1 += __shfl_xor_sync(0xffffffffu, rsum1, 1);
    rsum1 += __shfl_xor_sync(0xffffffffu, rsum1, 2);

    // ---- epilogue: stage O in smem (padded pitch), coalesced float4 stores ----
    __syncthreads();
    float* Obuf = reinterpret_cast<float*>(smem + OFF_ST);
    const float inv0 = 1.0f / rsum0;
    const float inv1 = 1.0f / rsum1;
    const int qc = wid * 16 + (lane >> 2);
#pragma unroll
    for (int n = 0; n < 8; ++n) {
        const int d0 = 8 * n + 2 * (lane & 3);
        Obuf[d0 * OPITCH + qc]           = O[n][0] * inv0;
        Obuf[(d0 + 1) * OPITCH + qc]     = O[n][1] * inv0;
        Obuf[d0 * OPITCH + qc + 8]       = O[n][2] * inv1;
        Obuf[(d0 + 1) * OPITCH + qc + 8] = O[n][3] * inv1;
    }
    __syncthreads();
#pragma unroll
    for (int i = 0; i < 8; ++i) {
        const int idx = i * 128 + tid;
        const int row = idx >> 4, c4 = idx & 15;
        float4 val = *reinterpret_cast<const float4*>(Obuf + row * OPITCH + c4 * 4);
        *reinterpret_cast<float4*>(outg + base + (size_t)row * LEN + qt + c4 * 4) = val;
    }
}

extern "C" void kernel_launch(void* const* d_in, const int* in_sizes, int n_in,
                              void* d_out, int out_size) {
    const float* q = (const float*)d_in[0];
    const float* k = (const float*)d_in[1];
    const float* v = (const float*)d_in[2];
    float* out = (float*)d_out;

    convert_split<<<1024, 256>>>(q, k, v);

    cudaFuncSetAttribute(attn_mma, cudaFuncAttributeMaxDynamicSharedMemorySize, SMEM_TOTAL);
    dim3 grid(LEN / TQ, BH);                      // (32, 32) = 1024 CTAs
    attn_mma<<<grid, 128, SMEM_TOTAL>>>(out);
}

// round 8
// speedup vs baseline: 10.9185x; 1.3382x over previous
#include <cuda_runtime.h>
#include <cuda_fp16.h>
#include <stdint.h>

// Attention_49194555408812: mma.sync fp16 single-pass both GEMMs, sm_103-safe.
// Round 8: Q,K,V,P all plain fp16 (error budget measured across rounds 6/7:
// each dropped 2^-11 residual pass adds ~2-3e-4 in quadrature; predicted ~5e-4).
// exp2-folded softmax, deferred rsum, 3 CTAs/SM, 3-stage cp.async ring.

namespace {
constexpr int D   = 64;
constexpr int LEN = 2048;
constexpr int BH  = 32;
constexpr int TQ  = 64;
constexpr int TK  = 64;
constexpr int NT  = LEN / TK;   // 32
constexpr float QSCALE = 0.125f * 1.4426950408889634f;   // 1/sqrt(64) * log2(e)
constexpr float NSLOPE = 0.01f;
constexpr int NELEM = BH * D * LEN;

constexpr int OFF_QH = 0;                   // [d=64][q=64] fp16, 128B rows
constexpr int OFF_ST = 8192;                // 3 stages x 16KB
constexpr int STAGE  = 16384;
constexpr int A_KH = 0, A_VH = 8192;
constexpr int SMEM_TOTAL = OFF_ST + 3 * STAGE;   // 57344 = 56 KB (3 CTAs/SM)
constexpr int OPITCH = 68;
}  // namespace

__device__ __align__(16) __half g_q[NELEM];
__device__ __align__(16) __half g_k[NELEM], g_v[NELEM];

__device__ __forceinline__ uint32_t swz128(uint32_t o) { return o ^ ((o >> 3) & 0x70); }

__device__ __forceinline__ uint32_t smem_u32(const void* p) {
    uint32_t a;
    asm("{ .reg .u64 t; cvta.to.shared.u64 t, %1; cvt.u32.u64 %0, t; }" : "=r"(a) : "l"(p));
    return a;
}
__device__ __forceinline__ void ldsm_x4_t(uint32_t addr, uint32_t& r0, uint32_t& r1,
                                          uint32_t& r2, uint32_t& r3) {
    asm volatile("ldmatrix.sync.aligned.m8n8.x4.trans.shared.b16 {%0,%1,%2,%3}, [%4];"
                 : "=r"(r0), "=r"(r1), "=r"(r2), "=r"(r3) : "r"(addr));
}
__device__ __forceinline__ void ldsm_x4(uint32_t addr, uint32_t& r0, uint32_t& r1,
                                        uint32_t& r2, uint32_t& r3) {
    asm volatile("ldmatrix.sync.aligned.m8n8.x4.shared.b16 {%0,%1,%2,%3}, [%4];"
                 : "=r"(r0), "=r"(r1), "=r"(r2), "=r"(r3) : "r"(addr));
}
__device__ __forceinline__ void mma16816(float c[4], const uint32_t a[4],
                                         uint32_t b0, uint32_t b1) {
    asm volatile(
        "mma.sync.aligned.m16n8k16.row.col.f32.f16.f16.f32 "
        "{%0,%1,%2,%3}, {%4,%5,%6,%7}, {%8,%9}, {%0,%1,%2,%3};"
        : "+f"(c[0]), "+f"(c[1]), "+f"(c[2]), "+f"(c[3])
        : "r"(a[0]), "r"(a[1]), "r"(a[2]), "r"(a[3]), "r"(b0), "r"(b1));
}
__device__ __forceinline__ uint32_t h2_bits(float a, float b) {
    __half2 h = __floats2half2_rn(a, b);
    return *reinterpret_cast<uint32_t*>(&h);
}
__device__ __forceinline__ float ex2(float x) {
    float y;
    asm("ex2.approx.f32 %0, %1;" : "=f"(y) : "f"(x));
    return y;
}

#define CP_ASYNC16(dst, src) \
    asm volatile("cp.async.cg.shared.global [%0], [%1], 16;" :: "r"(dst), "l"(src) : "memory")
#define CP_COMMIT() asm volatile("cp.async.commit_group;" ::: "memory")
#define CP_WAIT1()  asm volatile("cp.async.wait_group 1;" ::: "memory")

// ------------- pre-pass: Q -> fp16 (scaled by 1/8*log2e); K,V -> fp16 -------------
__global__ void convert_split(const float* __restrict__ q, const float* __restrict__ k,
                              const float* __restrict__ v) {
    const int NV4 = NELEM / 4;
    for (int i = blockIdx.x * blockDim.x + threadIdx.x; i < 3 * NV4;
         i += gridDim.x * blockDim.x) {
        const int t = i / NV4, j = i - t * NV4;
        const float* src = (t == 0) ? q : (t == 1) ? k : v;
        __half* dst = (t == 0) ? g_q : (t == 1) ? g_k : g_v;
        float4 f = reinterpret_cast<const float4*>(src)[j];
        if (t == 0) { f.x *= QSCALE; f.y *= QSCALE; f.z *= QSCALE; f.w *= QSCALE; }
        reinterpret_cast<uint2*>(dst)[j] =
            make_uint2(h2_bits(f.x, f.y), h2_bits(f.z, f.w));
    }
}

// ---------------- main kernel ----------------
__device__ __forceinline__ void issue_tile(uint32_t sbase, size_t hbase, int kt, int tid) {
    const __half* gsrc[2] = {g_k, g_v};
#pragma unroll
    for (int a = 0; a < 2; ++a) {
#pragma unroll
        for (int c = 0; c < 4; ++c) {
            const int ci = c * 128 + tid;        // 512 chunks of 16B per array
            const int d = ci >> 3, c8 = ci & 7;
            const void* src = gsrc[a] + hbase + (size_t)d * LEN + kt + c8 * 8;
            CP_ASYNC16(sbase + a * 8192 + swz128(d * 128 + c8 * 16), src);
        }
    }
}

__global__ void __launch_bounds__(128, 3)
attn_mma(float* __restrict__ outg) {
    extern __shared__ __align__(1024) char smem[];
    const uint32_t sb = smem_u32(smem);

    const int tid  = threadIdx.x;
    const int wid  = tid >> 5;
    const int lane = tid & 31;
    const int sub  = lane >> 3;
    const int li   = lane & 7;
    const int bh   = blockIdx.y;
    const int qt   = blockIdx.x * TQ;
    const size_t base = (size_t)bh * D * LEN;

    // prologue: Q + tile0 as group0; tile1 as group1
    {
#pragma unroll
        for (int c = 0; c < 4; ++c) {
            const int ci = c * 128 + tid;
            const int d = ci >> 3, c8 = ci & 7;
            const void* src = g_q + base + (size_t)d * LEN + qt + c8 * 8;
            CP_ASYNC16(sb + OFF_QH + swz128(d * 128 + c8 * 16), src);
        }
        issue_tile(sb + OFF_ST, base, 0, tid);
        CP_COMMIT();
        issue_tile(sb + OFF_ST + STAGE, base, TK, tid);
        CP_COMMIT();
    }
    CP_WAIT1();
    __syncthreads();

    // Q fragments (one-time)
    uint32_t QHf[4][4];
    {
        const int q0 = wid * 16 + ((sub & 1) << 3);
#pragma unroll
        for (int j = 0; j < 4; ++j) {
            const int dr = 16 * j + ((sub >> 1) << 3) + li;
            ldsm_x4_t(sb + OFF_QH + swz128(dr * 128 + q0 * 2),
                      QHf[j][0], QHf[j][1], QHf[j][2], QHf[j][3]);
        }
    }

    float O[8][4];
#pragma unroll
    for (int n = 0; n < 8; ++n)
#pragma unroll
        for (int c = 0; c < 4; ++c) O[n][c] = 0.0f;
    float rsum0 = 0.0f, rsum1 = 0.0f;   // per-thread partials (quad-reduced at end)

    int stg_idx = 0;
    for (int t = 0; t < NT; ++t) {
        if (t) { CP_WAIT1(); __syncthreads(); }
        const uint32_t stg = sb + OFF_ST + stg_idx * STAGE;

        // prefetch t+2 into the stage last read at t-1 (protected by barrier above)
        if (t + 2 < NT)
            issue_tile(sb + OFF_ST + ((stg_idx + 2) % 3) * STAGE, base, (t + 2) * TK, tid);
        CP_COMMIT();                              // uniform group count

        // ---- GEMM1: S' = Q·K  (log2e-scaled scores, single fp16 pass) ----
        float S[8][4];
#pragma unroll
        for (int n = 0; n < 8; ++n)
#pragma unroll
            for (int c = 0; c < 4; ++c) S[n][c] = 0.0f;
#pragma unroll
        for (int j = 0; j < 4; ++j) {
            const int dr = 16 * j + ((sub & 1) << 3) + li;
#pragma unroll
            for (int np = 0; np < 4; ++np) {
                const int nc = 16 * np + ((sub >> 1) << 3);
                uint32_t b0, b1, b2, b3;
                ldsm_x4_t(stg + A_KH + swz128(dr * 128 + nc * 2), b0, b1, b2, b3);
                mma16816(S[2 * np],     QHf[j], b0, b1);
                mma16816(S[2 * np + 1], QHf[j], b2, b3);
            }
        }

        // ---- p = 2^(leakyrelu(s'));  accumulate per-thread partial sums ----
        float t0 = 0.0f, t1 = 0.0f;
#pragma unroll
        for (int n = 0; n < 8; ++n) {
#pragma unroll
            for (int c = 0; c < 4; ++c) {
                float x = S[n][c];
                S[n][c] = ex2(fmaxf(x, NSLOPE * x));
            }
            t0 += S[n][0] + S[n][1];
            t1 += S[n][2] + S[n][3];
        }
        rsum0 += t0;
        rsum1 += t1;

        // ---- GEMM2: O += P·V (single fp16 pass, in-register repack) ----
#pragma unroll
        for (int j = 0; j < 4; ++j) {
            uint32_t ah[4];
            ah[0] = h2_bits(S[2 * j][0],     S[2 * j][1]);
            ah[1] = h2_bits(S[2 * j][2],     S[2 * j][3]);
            ah[2] = h2_bits(S[2 * j + 1][0], S[2 * j + 1][1]);
            ah[3] = h2_bits(S[2 * j + 1][2], S[2 * j + 1][3]);
            const int kc = 16 * j + ((sub & 1) << 3);
#pragma unroll
            for (int dp = 0; dp < 4; ++dp) {
                const int dr = 16 * dp + ((sub >> 1) << 3) + li;
                uint32_t b0, b1, b2, b3;
                ldsm_x4(stg + A_VH + swz128(dr * 128 + kc * 2), b0, b1, b2, b3);
                mma16816(O[2 * dp],     ah, b0, b1);
                mma16816(O[2 * dp + 1], ah, b2, b3);
            }
        }

        stg_idx = (stg_idx + 1) % 3;
    }

    // ---- deferred quad reduction of row sums ----
    rsum0 += __shfl_xor_sync(0xffffffffu, rsum0, 1);
    rsum0 += __shfl_xor_sync(0xffffffffu, rsum0, 2);
    rsum1 += __shfl_xor_sync(0xffffffffu, rsum1, 1);
    rsum1 += __shfl_xor_sync(0xffffffffu, rsum1, 2);

    // ---- epilogue: stage O in smem (padded pitch), coalesced float4 stores ----
    __syncthreads();
    float* Obuf = reinterpret_cast<float*>(smem + OFF_ST);
    const float inv0 = 1.0f / rsum0;
    const float inv1 = 1.0f / rsum1;
    const int qc = wid * 16 + (lane >> 2);
#pragma unroll
    for (int n = 0; n < 8; ++n) {
        const int d0 = 8 * n + 2 * (lane & 3);
        Obuf[d0 * OPITCH + qc]           = O[n][0] * inv0;
        Obuf[(d0 + 1) * OPITCH + qc]     = O[n][1] * inv0;
        Obuf[d0 * OPITCH + qc + 8]       = O[n][2] * inv1;
        Obuf[(d0 + 1) * OPITCH + qc + 8] = O[n][3] * inv1;
    }
    __syncthreads();
#pragma unroll
    for (int i = 0; i < 8; ++i) {
        const int idx = i * 128 + tid;
        const int row = idx >> 4, c4 = idx & 15;
        float4 val = *reinterpret_cast<const float4*>(Obuf + row * OPITCH + c4 * 4);
        *reinterpret_cast<float4*>(outg + base + (size_t)row * LEN + qt + c4 * 4) = val;
    }
}

extern "C" void kernel_launch(void* const* d_in, const int* in_sizes, int n_in,
                              void* d_out, int out_size) {
    const float* q = (const float*)d_in[0];
    const float* k = (const float*)d_in[1];
    const float* v = (const float*)d_in[2];
    float* out = (float*)d_out;

    convert_split<<<1024, 256>>>(q, k, v);

    cudaFuncSetAttribute(attn_mma, cudaFuncAttributeMaxDynamicSharedMemorySize, SMEM_TOTAL);
    dim3 grid(LEN / TQ, BH);                      // (32, 32) = 1024 CTAs
    attn_mma<<<grid, 128, SMEM_TOTAL>>>(out);
}